// round 15
// baseline (speedup 1.0000x reference)
#include <cuda_runtime.h>
#include <math.h>
#include <stdint.h>

#define BATCH 4
#define SEQ   2048
#define EMD   768
#define HEADS 8
#define HDIM  96
#define MROWS (BATCH*SEQ)

#define TQ 32
#define TK 16
#define KSPLIT 4
#define KCHUNK (SEQ/KSPLIT)
#define QSTR 776           // bf16 elements per smem row (attention)
#define ESTR 18
#define GSTR 40            // bf16 elements per smem row (GEMM BK=32 + pad)
#define SQRT_EMD 27.712812921102035f

// C(16x8,f32) += A(16x16,bf16,row) * B(16x8,bf16,col)
__device__ __forceinline__ void mma_bf16(float* d, const uint32_t* a, const uint32_t* b) {
    asm volatile(
        "mma.sync.aligned.m16n8k16.row.col.f32.bf16.bf16.f32 "
        "{%0,%1,%2,%3}, {%4,%5,%6,%7}, {%8,%9}, {%0,%1,%2,%3};"
        : "+f"(d[0]), "+f"(d[1]), "+f"(d[2]), "+f"(d[3])
        : "r"(a[0]), "r"(a[1]), "r"(a[2]), "r"(a[3]), "r"(b[0]), "r"(b[1]));
}
__device__ __forceinline__ uint32_t bfx2(float lo, float hi) {
    uint32_t r; asm("cvt.rn.bf16x2.f32 %0, %1, %2;" : "=r"(r) : "f"(hi), "f"(lo)); return r;
}
// split (x,y) into hi-pair (bf16 rn) and lo-pair (residual as bf16); lo half = x
__device__ __forceinline__ void split2(float x, float y, uint32_t& hp, uint32_t& lp) {
    const uint32_t bx = __float_as_uint(x), by = __float_as_uint(y);
    const uint32_t rx = (bx + 0x7FFFu + ((bx >> 16) & 1u)) & 0xFFFF0000u;
    const uint32_t ry = (by + 0x7FFFu + ((by >> 16) & 1u)) & 0xFFFF0000u;
    hp = ry | (rx >> 16);
    lp = bfx2(x - __uint_as_float(rx), y - __uint_as_float(ry));
}
__device__ __forceinline__ uint32_t smem_u32(const void* p) {
    uint32_t a;
    asm("{ .reg .u64 t; cvta.to.shared.u64 t, %1; cvt.u32.u64 %0, t; }" : "=r"(a) : "l"(p));
    return a;
}
__device__ __forceinline__ void ldmx4(uint32_t* r, uint32_t addr) {
    asm volatile("ldmatrix.sync.aligned.m8n8.x4.shared.b16 {%0,%1,%2,%3}, [%4];"
                 : "=r"(r[0]), "=r"(r[1]), "=r"(r[2]), "=r"(r[3]) : "r"(addr));
}
__device__ __forceinline__ void ldmx2(uint32_t* r, uint32_t addr) {
    asm volatile("ldmatrix.sync.aligned.m8n8.x2.shared.b16 {%0,%1}, [%2];"
                 : "=r"(r[0]), "=r"(r[1]) : "r"(addr));
}
// 2x 8x8 b16 transposed tiles (B-fragment for AV)
__device__ __forceinline__ void ldmx2t(uint32_t& b0, uint32_t& b1, uint32_t addr) {
    asm volatile("ldmatrix.sync.aligned.m8n8.x2.trans.shared.b16 {%0,%1}, [%2];"
                 : "=r"(b0), "=r"(b1) : "r"(addr));
}

// Scratch (allocation-free rule: __device__ globals)
__device__ uint16_t g_Qhi[MROWS*EMD], g_Qlo[MROWS*EMD];
__device__ uint16_t g_Khi[MROWS*EMD], g_Klo[MROWS*EMD];
__device__ uint16_t g_Vhi[MROWS*EMD], g_Vlo[MROWS*EMD];
__device__ float g_O0[MROWS*EMD];
__device__ float g_O1[MROWS*EMD];
__device__ float g_O2[MROWS*EMD];
__device__ float g_O3[MROWS*EMD];

// ---------------------------------------------------------------------------
// split-bf16 NT GEMM: C = A*W^T + bias, all products in 3x m16n8k16 bf16
// (hi*hi + hi*lo + lo*hi; error ~2^-18, fp32-class). 128x128 tile, BK=32,
// 8 warps (2M x 4N), fragments via ldmatrix, 2 CTAs/SM.
// Output: fp32 C (H==0) or split-bf16 hi/lo planes (attention inputs).
// blockIdx.z selects the (W,bias,out) triple for the fused QKV launch.
// ---------------------------------------------------------------------------
__global__ __launch_bounds__(256, 2)
void gemm_bf16(const float* __restrict__ A,
               const float* __restrict__ W0, const float* __restrict__ bv0, float* __restrict__ C0,
               uint16_t* __restrict__ H0, uint16_t* __restrict__ L0,
               const float* __restrict__ W1, const float* __restrict__ bv1, float* __restrict__ C1,
               uint16_t* __restrict__ H1, uint16_t* __restrict__ L1,
               const float* __restrict__ W2, const float* __restrict__ bv2, float* __restrict__ C2,
               uint16_t* __restrict__ H2, uint16_t* __restrict__ L2)
{
    const float* W    = W0;
    const float* bias = bv0;
    float*       C    = C0;
    uint16_t*    H    = H0;
    uint16_t*    L    = L0;
    if (blockIdx.z == 1) { W = W1; bias = bv1; C = C1; H = H1; L = L1; }
    if (blockIdx.z == 2) { W = W2; bias = bv2; C = C2; H = H2; L = L2; }

    __shared__ __align__(16) uint16_t Ahi[128*GSTR], Alo[128*GSTR];
    __shared__ __align__(16) uint16_t Bhi[128*GSTR], Blo[128*GSTR];

    const int tid  = threadIdx.x;
    const int w    = tid >> 5;
    const int lane = tid & 31;
    const int wm   = w & 1;          // 2 M-warps of 64 rows
    const int wn   = w >> 1;         // 4 N-warps of 32 cols
    const int gid  = lane >> 2;
    const int tig  = lane & 3;
    const int m0   = blockIdx.x * 128;
    const int n0   = blockIdx.y * 128;

    const int lr = tid >> 1;         // fill row 0..127
    const int lc = (tid & 1) * 16;   // fill col 0 or 16

    const float* Ap = A + (size_t)(m0 + lr) * EMD + lc;
    const float* Wp = W + (size_t)(n0 + lr) * EMD + lc;

    // ldmatrix per-lane address offsets (element units within a plane)
    const int l15   = lane & 15;
    const int aOff  = (wm*64 + l15) * GSTR + ((lane >> 4) << 3);    // + i*16*GSTR + kt*16
    const int bOff  = (wn*32 + (l15 & 7)) * GSTR + ((l15 >> 3) << 3); // + j*8*GSTR + kt*16

    const uint32_t smAh = smem_u32(Ahi), smAl = smem_u32(Alo);
    const uint32_t smBh = smem_u32(Bhi), smBl = smem_u32(Blo);

    float acc[4][4][4];
    #pragma unroll
    for (int i = 0; i < 4; i++)
        #pragma unroll
        for (int j = 0; j < 4; j++)
            #pragma unroll
            for (int r = 0; r < 4; r++) acc[i][j][r] = 0.f;

    for (int k0 = 0; k0 < EMD; k0 += 32) {
        // ---- fill: 16 A + 16 W floats per thread -> hi/lo bf16 planes ----
        {
            uint32_t h[8], l[8];
            #pragma unroll
            for (int ci = 0; ci < 4; ci++) {
                const float4 v = *(const float4*)(Ap + k0 + ci*4);
                split2(v.x, v.y, h[ci*2+0], l[ci*2+0]);
                split2(v.z, v.w, h[ci*2+1], l[ci*2+1]);
            }
            uint4 u;
            u.x=h[0]; u.y=h[1]; u.z=h[2]; u.w=h[3]; *(uint4*)&Ahi[lr*GSTR+lc]   = u;
            u.x=h[4]; u.y=h[5]; u.z=h[6]; u.w=h[7]; *(uint4*)&Ahi[lr*GSTR+lc+8] = u;
            u.x=l[0]; u.y=l[1]; u.z=l[2]; u.w=l[3]; *(uint4*)&Alo[lr*GSTR+lc]   = u;
            u.x=l[4]; u.y=l[5]; u.z=l[6]; u.w=l[7]; *(uint4*)&Alo[lr*GSTR+lc+8] = u;
            #pragma unroll
            for (int ci = 0; ci < 4; ci++) {
                const float4 v = *(const float4*)(Wp + k0 + ci*4);
                split2(v.x, v.y, h[ci*2+0], l[ci*2+0]);
                split2(v.z, v.w, h[ci*2+1], l[ci*2+1]);
            }
            u.x=h[0]; u.y=h[1]; u.z=h[2]; u.w=h[3]; *(uint4*)&Bhi[lr*GSTR+lc]   = u;
            u.x=h[4]; u.y=h[5]; u.z=h[6]; u.w=h[7]; *(uint4*)&Bhi[lr*GSTR+lc+8] = u;
            u.x=l[0]; u.y=l[1]; u.z=l[2]; u.w=l[3]; *(uint4*)&Blo[lr*GSTR+lc]   = u;
            u.x=l[4]; u.y=l[5]; u.z=l[6]; u.w=l[7]; *(uint4*)&Blo[lr*GSTR+lc+8] = u;
        }
        __syncthreads();

        // ---- compute: 2 k16-tiles, frags via ldmatrix, 96 bf16 MMAs ----
        #pragma unroll
        for (int kt = 0; kt < 2; kt++) {
            uint32_t ah[4][4], al[4][4], bh[4][2], bl[4][2];
            #pragma unroll
            for (int i = 0; i < 4; i++) {
                const uint32_t off = (uint32_t)(aOff + i*16*GSTR + kt*16) * 2u;
                ldmx4(ah[i], smAh + off);
                ldmx4(al[i], smAl + off);
            }
            #pragma unroll
            for (int j = 0; j < 4; j++) {
                const uint32_t off = (uint32_t)(bOff + j*8*GSTR + kt*16) * 2u;
                ldmx2(bh[j], smBh + off);
                ldmx2(bl[j], smBl + off);
            }
            #pragma unroll
            for (int i = 0; i < 4; i++)
                #pragma unroll
                for (int j = 0; j < 4; j++) {
                    mma_bf16(acc[i][j], ah[i], bh[j]);
                    mma_bf16(acc[i][j], ah[i], bl[j]);
                    mma_bf16(acc[i][j], al[i], bh[j]);
                }
        }
        __syncthreads();
    }

    #pragma unroll
    for (int i = 0; i < 4; i++) {
        const int m = m0 + wm*64 + i*16 + gid;
        #pragma unroll
        for (int j = 0; j < 4; j++) {
            const int n = n0 + wn*32 + j*8 + tig*2;
            const float2 bv = *(const float2*)&bias[n];
            float2 o0, o1;
            o0.x = acc[i][j][0] + bv.x; o0.y = acc[i][j][1] + bv.y;
            o1.x = acc[i][j][2] + bv.x; o1.y = acc[i][j][3] + bv.y;
            if (H) {   // split-bf16 hi/lo plane output (attention inputs)
                uint32_t hp, lp;
                split2(o0.x, o0.y, hp, lp);
                *(uint32_t*)(H + (size_t)m*EMD + n) = hp;
                *(uint32_t*)(L + (size_t)m*EMD + n) = lp;
                split2(o1.x, o1.y, hp, lp);
                *(uint32_t*)(H + (size_t)(m+8)*EMD + n) = hp;
                *(uint32_t*)(L + (size_t)(m+8)*EMD + n) = lp;
            } else {
                *(float2*)(C + (size_t)m*EMD + n)     = o0;
                *(float2*)(C + (size_t)(m+8)*EMD + n) = o1;
            }
        }
    }
}

// ---------------------------------------------------------------------------
// Sum the 4 split-K partial O buffers into g_O0 (float4 grid-stride).
// ---------------------------------------------------------------------------
__global__ __launch_bounds__(256)
void presum_o()
{
    const size_t N = (size_t)MROWS * EMD / 4;
    float4*       o0 = (float4*)g_O0;
    const float4* o1 = (const float4*)g_O1;
    const float4* o2 = (const float4*)g_O2;
    const float4* o3 = (const float4*)g_O3;
    for (size_t i = (size_t)blockIdx.x * blockDim.x + threadIdx.x; i < N;
         i += (size_t)gridDim.x * blockDim.x) {
        float4 a = o0[i];
        const float4 b = o1[i], c = o2[i], d = o3[i];
        a.x = (a.x + b.x) + (c.x + d.x);
        a.y = (a.y + b.y) + (c.y + d.y);
        a.z = (a.z + b.z) + (c.z + d.z);
        a.w = (a.w + b.w) + (c.w + d.w);
        o0[i] = a;
    }
}

// ---------------------------------------------------------------------------
// Fused attention, softmax over HEADS axis. Split-K4, TQ=32. (unchanged R14)
// E  = Q K^T  via split-bf16 m16n8k16 (hi/lo planes precomputed in GEMM).
// AV = A V    via split-bf16 m16n8k16 with A-frags built in registers from the
//              E C-frags (identical layout), scaled by cross-head 1/denom;
//              V B-frags via ldmatrix.x2.trans.
// ---------------------------------------------------------------------------
__global__ __launch_bounds__(256)
void attn_kernel()
{
    extern __shared__ char smx[];
    uint16_t* Qhi = (uint16_t*)(smx);            // 49664
    uint16_t* Qlo = (uint16_t*)(smx + 49664);    // 49664
    uint16_t* Khi = (uint16_t*)(smx + 99328);    // 24832
    uint16_t* Klo = (uint16_t*)(smx + 124160);   // 24832
    uint16_t* Vhi = (uint16_t*)(smx + 148992);   // 24832
    uint16_t* Vlo = (uint16_t*)(smx + 173824);   // 24832
    float*    Es  = (float*)   (smx + 198656);   // 18432
    float*    Dinv= (float*)   (smx + 217088);   // 2304

    const int b    = blockIdx.y;
    const int q0   = blockIdx.x * TQ;
    const int kh   = blockIdx.z;
    const int tid  = threadIdx.x;
    const int warp = tid >> 5;              // head
    const int lane = tid & 31;
    const int gid  = lane >> 2;             // 0..7
    const int tig  = lane & 3;              // 0..3
    const int hb   = warp * HDIM;           // head col base

    // ---- Q planes -> smem (once per CTA) ----
    for (int j = tid; j < TQ*(EMD/8); j += 256) {
        const int r  = j / (EMD/8);
        const int c8 = (j % (EMD/8)) * 8;
        const size_t g = (size_t)(b*SEQ + q0 + r)*EMD + c8;
        *(uint4*)(Qhi + (size_t)r*QSTR + c8) = *(const uint4*)(g_Qhi + g);
        *(uint4*)(Qlo + (size_t)r*QSTR + c8) = *(const uint4*)(g_Qlo + g);
    }

    float Oacc[2][12][4];
    #pragma unroll
    for (int i = 0; i < 2; i++)
        #pragma unroll
        for (int jj = 0; jj < 12; jj++)
            #pragma unroll
            for (int r = 0; r < 4; r++) Oacc[i][jj][r] = 0.f;

    const uint32_t vhiA = smem_u32(Vhi) + (uint32_t)((lane & 15) * QSTR + hb) * 2u;
    const uint32_t vloA = smem_u32(Vlo) + (uint32_t)((lane & 15) * QSTR + hb) * 2u;

    const int kbeg = kh * KCHUNK;
    for (int k0 = kbeg; k0 < kbeg + KCHUNK; k0 += TK) {
        __syncthreads();

        for (int j = tid; j < TK*(EMD/8); j += 256) {
            const int r  = j / (EMD/8);
            const int c8 = (j % (EMD/8)) * 8;
            const size_t g = (size_t)(b*SEQ + k0 + r)*EMD + c8;
            const size_t so = (size_t)r*QSTR + c8;
            *(uint4*)(Khi + so) = *(const uint4*)(g_Khi + g);
            *(uint4*)(Klo + so) = *(const uint4*)(g_Klo + g);
            *(uint4*)(Vhi + so) = *(const uint4*)(g_Vhi + g);
            *(uint4*)(Vlo + so) = *(const uint4*)(g_Vlo + g);
        }
        __syncthreads();

        // ---- E = Q K^T : 32x16 per warp, split-bf16, 72 MMAs ----
        float eacc[2][2][4];
        #pragma unroll
        for (int i = 0; i < 2; i++)
            #pragma unroll
            for (int j = 0; j < 2; j++)
                #pragma unroll
                for (int r = 0; r < 4; r++) eacc[i][j][r] = 0.f;

        #pragma unroll
        for (int s = 0; s < 6; s++) {
            const int cA = hb + s*16 + tig*2;
            uint32_t ah[2][4], al[2][4], bh[2][2], bl[2][2];
            #pragma unroll
            for (int i = 0; i < 2; i++) {
                const size_t ro = (size_t)(i*16 + gid)*QSTR + cA;
                const uint16_t* ph = Qhi + ro;
                ah[i][0] = *(const uint32_t*)(ph);
                ah[i][1] = *(const uint32_t*)(ph + (size_t)8*QSTR);
                ah[i][2] = *(const uint32_t*)(ph + 8);
                ah[i][3] = *(const uint32_t*)(ph + (size_t)8*QSTR + 8);
                const uint16_t* pl = Qlo + ro;
                al[i][0] = *(const uint32_t*)(pl);
                al[i][1] = *(const uint32_t*)(pl + (size_t)8*QSTR);
                al[i][2] = *(const uint32_t*)(pl + 8);
                al[i][3] = *(const uint32_t*)(pl + (size_t)8*QSTR + 8);
            }
            #pragma unroll
            for (int j = 0; j < 2; j++) {
                const size_t ro = (size_t)(j*8 + gid)*QSTR + cA;
                const uint16_t* ph = Khi + ro;
                bh[j][0] = *(const uint32_t*)(ph);
                bh[j][1] = *(const uint32_t*)(ph + 8);
                const uint16_t* pl = Klo + ro;
                bl[j][0] = *(const uint32_t*)(pl);
                bl[j][1] = *(const uint32_t*)(pl + 8);
            }
            #pragma unroll
            for (int i = 0; i < 2; i++)
                #pragma unroll
                for (int j = 0; j < 2; j++) {
                    mma_bf16(eacc[i][j], ah[i], bh[j]);
                    mma_bf16(eacc[i][j], ah[i], bl[j]);
                    mma_bf16(eacc[i][j], al[i], bh[j]);
                }
        }

        // ---- exp in registers; copies to Es for the denominator ----
        float ex[2][2][4];
        #pragma unroll
        for (int i = 0; i < 2; i++) {
            const int r0 = warp*TQ + i*16 + gid;
            #pragma unroll
            for (int j = 0; j < 2; j++) {
                const int c0 = j*8 + tig*2;
                ex[i][j][0] = __expf(eacc[i][j][0]);
                ex[i][j][1] = __expf(eacc[i][j][1]);
                ex[i][j][2] = __expf(eacc[i][j][2]);
                ex[i][j][3] = __expf(eacc[i][j][3]);
                float2 e0; e0.x = ex[i][j][0]; e0.y = ex[i][j][1];
                float2 e1; e1.x = ex[i][j][2]; e1.y = ex[i][j][3];
                *(float2*)&Es[(r0    )*ESTR + c0] = e0;
                *(float2*)&Es[(r0 + 8)*ESTR + c0] = e1;
            }
        }
        __syncthreads();

        // ---- cross-head denominator -> Dinv ----
        #pragma unroll
        for (int pp = 0; pp < 2; pp++) {
            const int p = tid*2 + pp;
            const int q = p >> 4;
            const int k = p & 15;
            float s = 0.f;
            #pragma unroll
            for (int h = 0; h < HEADS; h++) s += Es[(h*TQ + q)*ESTR + k];
            Dinv[q*ESTR + k] = 1.0f / (s * SQRT_EMD);
        }
        __syncthreads();

        // ---- A-fragments in registers: a = exp * inv, split-bf16 ----
        uint32_t Ah[2][4], Al[2][4];
        #pragma unroll
        for (int i = 0; i < 2; i++) {
            const int r0 = (i*16 + gid)*ESTR;
            const int r1 = (i*16 + gid + 8)*ESTR;
            const float2 i00 = *(const float2*)&Dinv[r0 + tig*2];
            const float2 i10 = *(const float2*)&Dinv[r1 + tig*2];
            const float2 i01 = *(const float2*)&Dinv[r0 + tig*2 + 8];
            const float2 i11 = *(const float2*)&Dinv[r1 + tig*2 + 8];
            split2(ex[i][0][0]*i00.x, ex[i][0][1]*i00.y, Ah[i][0], Al[i][0]);
            split2(ex[i][0][2]*i10.x, ex[i][0][3]*i10.y, Ah[i][1], Al[i][1]);
            split2(ex[i][1][0]*i01.x, ex[i][1][1]*i01.y, Ah[i][2], Al[i][2]);
            split2(ex[i][1][2]*i11.x, ex[i][1][3]*i11.y, Ah[i][3], Al[i][3]);
        }

        // ---- O += A @ V : V B-frags via ldmatrix.trans, 72 MMAs ----
        #pragma unroll
        for (int jj = 0; jj < 12; jj++) {
            uint32_t bh[2], bl[2];
            ldmx2t(bh[0], bh[1], vhiA + jj*16);
            ldmx2t(bl[0], bl[1], vloA + jj*16);
            #pragma unroll
            for (int i = 0; i < 2; i++) {
                mma_bf16(Oacc[i][jj], Ah[i], bh);
                mma_bf16(Oacc[i][jj], Ah[i], bl);
                mma_bf16(Oacc[i][jj], Al[i], bh);
            }
        }
    }

    // ---- write partial O in [M, 768] layout ----
    float* Obase = (kh == 0) ? g_O0 : (kh == 1) ? g_O1 : (kh == 2) ? g_O2 : g_O3;
    #pragma unroll
    for (int i = 0; i < 2; i++) {
        const size_t r0 = (size_t)(b*SEQ + q0 + i*16 + gid);
        #pragma unroll
        for (int jj = 0; jj < 12; jj++) {
            const int n = hb + jj*8 + tig*2;
            float2 o0; o0.x = Oacc[i][jj][0]; o0.y = Oacc[i][jj][1];
            float2 o1; o1.x = Oacc[i][jj][2]; o1.y = Oacc[i][jj][3];
            *(float2*)(Obase + r0*EMD + n)       = o0;
            *(float2*)(Obase + (r0+8)*EMD + n)   = o1;
        }
    }
}

// ---------------------------------------------------------------------------
extern "C" void kernel_launch(void* const* d_in, const int* in_sizes, int n_in,
                              void* d_out, int out_size)
{
    const float* x  = (const float*)d_in[0];
    const float* Wq = (const float*)d_in[1];
    const float* bq = (const float*)d_in[2];
    const float* Wk = (const float*)d_in[3];
    const float* bk = (const float*)d_in[4];
    const float* Wv = (const float*)d_in[5];
    const float* bv = (const float*)d_in[6];
    const float* Wo = (const float*)d_in[7];
    const float* bo = (const float*)d_in[8];
    float* out = (float*)d_out;

    float *O0p;
    uint16_t *Qh, *Ql, *Kh, *Kl, *Vh, *Vl;
    cudaGetSymbolAddress((void**)&O0p, g_O0);
    cudaGetSymbolAddress((void**)&Qh,  g_Qhi);
    cudaGetSymbolAddress((void**)&Ql,  g_Qlo);
    cudaGetSymbolAddress((void**)&Kh,  g_Khi);
    cudaGetSymbolAddress((void**)&Kl,  g_Klo);
    cudaGetSymbolAddress((void**)&Vh,  g_Vhi);
    cudaGetSymbolAddress((void**)&Vl,  g_Vlo);

    const int smem_bytes = 219392;
    cudaFuncSetAttribute(attn_kernel, cudaFuncAttributeMaxDynamicSharedMemorySize, smem_bytes);

    // 1) Fused QKV projections (split-bf16 GEMM) -> hi/lo planes
    gemm_bf16<<<dim3(MROWS/128, EMD/128, 3), 256>>>(
        x,
        Wq, bq, (float*)0, Qh, Ql,
        Wk, bk, (float*)0, Kh, Kl,
        Wv, bv, (float*)0, Vh, Vl);

    // 2) Fused head-axis-softmax attention, split-K4, tensor-pipe core
    attn_kernel<<<dim3(SEQ/TQ, BATCH, KSPLIT), 256, smem_bytes>>>();

    // 3) Sum split-K partials into g_O0
    presum_o<<<2048, 256>>>();

    // 4) Output projection (split-bf16 GEMM, fp32 out) -> d_out
    gemm_bf16<<<dim3(MROWS/128, EMD/128, 1), 256>>>(
        O0p,
        Wo, bo, out, (uint16_t*)0, (uint16_t*)0,
        Wo, bo, out, (uint16_t*)0, (uint16_t*)0,
        Wo, bo, out, (uint16_t*)0, (uint16_t*)0);
}

// round 16
// speedup vs baseline: 1.3355x; 1.3355x over previous
#include <cuda_runtime.h>
#include <math.h>
#include <stdint.h>

#define BATCH 4
#define SEQ   2048
#define EMD   768
#define HEADS 8
#define HDIM  96
#define MROWS (BATCH*SEQ)

#define TQ 32
#define TK 16
#define KSPLIT 4
#define KCHUNK (SEQ/KSPLIT)
#define QSTR 776           // bf16 elements per smem row (attention)
#define ESTR 18
#define GSTR 40            // bf16 elements per smem row (GEMM BK=32 + pad)
#define SQRT_EMD 27.712812921102035f

// C(16x8,f32) += A(16x16,bf16,row) * B(16x8,bf16,col)
__device__ __forceinline__ void mma_bf16(float* d, const uint32_t* a, const uint32_t* b) {
    asm volatile(
        "mma.sync.aligned.m16n8k16.row.col.f32.bf16.bf16.f32 "
        "{%0,%1,%2,%3}, {%4,%5,%6,%7}, {%8,%9}, {%0,%1,%2,%3};"
        : "+f"(d[0]), "+f"(d[1]), "+f"(d[2]), "+f"(d[3])
        : "r"(a[0]), "r"(a[1]), "r"(a[2]), "r"(a[3]), "r"(b[0]), "r"(b[1]));
}
__device__ __forceinline__ uint32_t bfx2(float lo, float hi) {
    uint32_t r; asm("cvt.rn.bf16x2.f32 %0, %1, %2;" : "=r"(r) : "f"(hi), "f"(lo)); return r;
}
// split (x,y) into hi-pair (bf16 rn) and lo-pair (residual as bf16); lo half = x
__device__ __forceinline__ void split2(float x, float y, uint32_t& hp, uint32_t& lp) {
    const uint32_t bx = __float_as_uint(x), by = __float_as_uint(y);
    const uint32_t rx = (bx + 0x7FFFu + ((bx >> 16) & 1u)) & 0xFFFF0000u;
    const uint32_t ry = (by + 0x7FFFu + ((by >> 16) & 1u)) & 0xFFFF0000u;
    hp = ry | (rx >> 16);
    lp = bfx2(x - __uint_as_float(rx), y - __uint_as_float(ry));
}
__device__ __forceinline__ uint32_t smem_u32(const void* p) {
    uint32_t a;
    asm("{ .reg .u64 t; cvta.to.shared.u64 t, %1; cvt.u32.u64 %0, t; }" : "=r"(a) : "l"(p));
    return a;
}
__device__ __forceinline__ void ldmx4(uint32_t* r, uint32_t addr) {
    asm volatile("ldmatrix.sync.aligned.m8n8.x4.shared.b16 {%0,%1,%2,%3}, [%4];"
                 : "=r"(r[0]), "=r"(r[1]), "=r"(r[2]), "=r"(r[3]) : "r"(addr));
}
__device__ __forceinline__ void ldmx2(uint32_t* r, uint32_t addr) {
    asm volatile("ldmatrix.sync.aligned.m8n8.x2.shared.b16 {%0,%1}, [%2];"
                 : "=r"(r[0]), "=r"(r[1]) : "r"(addr));
}
__device__ __forceinline__ void ldmx2t(uint32_t& b0, uint32_t& b1, uint32_t addr) {
    asm volatile("ldmatrix.sync.aligned.m8n8.x2.trans.shared.b16 {%0,%1}, [%2];"
                 : "=r"(b0), "=r"(b1) : "r"(addr));
}
__device__ __forceinline__ void cpa16(uint32_t saddr, const void* gaddr) {
    asm volatile("cp.async.cg.shared.global [%0], [%1], 16;" :: "r"(saddr), "l"(gaddr) : "memory");
}
#define CP_COMMIT() asm volatile("cp.async.commit_group;" ::: "memory")
#define CP_WAIT(n)  asm volatile("cp.async.wait_group %0;" :: "n"(n) : "memory")

// Scratch (allocation-free rule: __device__ globals)
__device__ uint16_t g_Qhi[MROWS*EMD], g_Qlo[MROWS*EMD];
__device__ uint16_t g_Khi[MROWS*EMD], g_Klo[MROWS*EMD];
__device__ uint16_t g_Vhi[MROWS*EMD], g_Vlo[MROWS*EMD];
__device__ uint16_t g_xhi[MROWS*EMD], g_xlo[MROWS*EMD];
__device__ uint16_t g_Ohi[MROWS*EMD], g_Olo[MROWS*EMD];
__device__ uint16_t g_Wqh[EMD*EMD], g_Wql[EMD*EMD];
__device__ uint16_t g_Wkh[EMD*EMD], g_Wkl[EMD*EMD];
__device__ uint16_t g_Wvh[EMD*EMD], g_Wvl[EMD*EMD];
__device__ uint16_t g_Woh[EMD*EMD], g_Wol[EMD*EMD];
__device__ float g_O0[MROWS*EMD];
__device__ float g_O1[MROWS*EMD];
__device__ float g_O2[MROWS*EMD];
__device__ float g_O3[MROWS*EMD];

// ---------------------------------------------------------------------------
// Elementwise split: fp32 -> bf16 hi/lo planes (float4 grid-stride).
// ---------------------------------------------------------------------------
__global__ __launch_bounds__(256)
void split_f32(const float* __restrict__ src, uint16_t* __restrict__ hi,
               uint16_t* __restrict__ lo, int n4)
{
    for (int i = blockIdx.x*256 + threadIdx.x; i < n4; i += gridDim.x*256) {
        const float4 v = ((const float4*)src)[i];
        uint32_t h0, l0, h1, l1;
        split2(v.x, v.y, h0, l0);
        split2(v.z, v.w, h1, l1);
        uint2 hh; hh.x = h0; hh.y = h1;
        uint2 ll; ll.x = l0; ll.y = l1;
        *(uint2*)(hi + (size_t)i*4) = hh;
        *(uint2*)(lo + (size_t)i*4) = ll;
    }
}

// ---------------------------------------------------------------------------
// split-bf16 NT GEMM from PRE-SPLIT hi/lo planes: C = A*W^T + bias via
// 3x m16n8k16 (hh+hl+lh). 128x128 tile, BK=32, 8 warps (2M x 4N),
// ldmatrix fragments, 2 CTAs/SM. Output: fp32 C (H==0) or hi/lo planes.
// blockIdx.z selects the (W,bias,out) triple for the fused QKV launch.
// ---------------------------------------------------------------------------
__global__ __launch_bounds__(256, 2)
void gemm_bf16(const uint16_t* __restrict__ Ah_g, const uint16_t* __restrict__ Al_g,
               const uint16_t* __restrict__ Wh0, const uint16_t* __restrict__ Wl0,
               const float* __restrict__ bv0, float* __restrict__ C0,
               uint16_t* __restrict__ H0, uint16_t* __restrict__ L0,
               const uint16_t* __restrict__ Wh1, const uint16_t* __restrict__ Wl1,
               const float* __restrict__ bv1, float* __restrict__ C1,
               uint16_t* __restrict__ H1, uint16_t* __restrict__ L1,
               const uint16_t* __restrict__ Wh2, const uint16_t* __restrict__ Wl2,
               const float* __restrict__ bv2, float* __restrict__ C2,
               uint16_t* __restrict__ H2, uint16_t* __restrict__ L2)
{
    const uint16_t* Wh = Wh0;
    const uint16_t* Wl = Wl0;
    const float* bias  = bv0;
    float*       C     = C0;
    uint16_t*    H     = H0;
    uint16_t*    L     = L0;
    if (blockIdx.z == 1) { Wh = Wh1; Wl = Wl1; bias = bv1; C = C1; H = H1; L = L1; }
    if (blockIdx.z == 2) { Wh = Wh2; Wl = Wl2; bias = bv2; C = C2; H = H2; L = L2; }

    __shared__ __align__(16) uint16_t Ahi[128*GSTR], Alo[128*GSTR];
    __shared__ __align__(16) uint16_t Bhi[128*GSTR], Blo[128*GSTR];

    const int tid  = threadIdx.x;
    const int w    = tid >> 5;
    const int lane = tid & 31;
    const int wm   = w & 1;
    const int wn   = w >> 1;
    const int gid  = lane >> 2;
    const int tig  = lane & 3;
    const int m0   = blockIdx.x * 128;
    const int n0   = blockIdx.y * 128;

    const int lr = tid >> 1;
    const int lc = (tid & 1) * 16;

    const uint16_t* pAh = Ah_g + (size_t)(m0 + lr) * EMD + lc;
    const uint16_t* pAl = Al_g + (size_t)(m0 + lr) * EMD + lc;
    const uint16_t* pWh = Wh   + (size_t)(n0 + lr) * EMD + lc;
    const uint16_t* pWl = Wl   + (size_t)(n0 + lr) * EMD + lc;

    const int l15  = lane & 15;
    const int aOff = (wm*64 + l15) * GSTR + ((lane >> 4) << 3);
    const int bOff = (wn*32 + (l15 & 7)) * GSTR + ((l15 >> 3) << 3);

    const uint32_t smAh = smem_u32(Ahi), smAl = smem_u32(Alo);
    const uint32_t smBh = smem_u32(Bhi), smBl = smem_u32(Blo);

    float acc[4][4][4];
    #pragma unroll
    for (int i = 0; i < 4; i++)
        #pragma unroll
        for (int j = 0; j < 4; j++)
            #pragma unroll
            for (int r = 0; r < 4; r++) acc[i][j][r] = 0.f;

    for (int k0 = 0; k0 < EMD; k0 += 32) {
        // ---- fill: plain uint4 copies from pre-split planes ----
        *(uint4*)&Ahi[lr*GSTR+lc]   = *(const uint4*)(pAh + k0);
        *(uint4*)&Ahi[lr*GSTR+lc+8] = *(const uint4*)(pAh + k0 + 8);
        *(uint4*)&Alo[lr*GSTR+lc]   = *(const uint4*)(pAl + k0);
        *(uint4*)&Alo[lr*GSTR+lc+8] = *(const uint4*)(pAl + k0 + 8);
        *(uint4*)&Bhi[lr*GSTR+lc]   = *(const uint4*)(pWh + k0);
        *(uint4*)&Bhi[lr*GSTR+lc+8] = *(const uint4*)(pWh + k0 + 8);
        *(uint4*)&Blo[lr*GSTR+lc]   = *(const uint4*)(pWl + k0);
        *(uint4*)&Blo[lr*GSTR+lc+8] = *(const uint4*)(pWl + k0 + 8);
        __syncthreads();

        // ---- compute: 2 k16-tiles, frags via ldmatrix, 96 bf16 MMAs ----
        #pragma unroll
        for (int kt = 0; kt < 2; kt++) {
            uint32_t ah[4][4], al[4][4], bh[4][2], bl[4][2];
            #pragma unroll
            for (int i = 0; i < 4; i++) {
                const uint32_t off = (uint32_t)(aOff + i*16*GSTR + kt*16) * 2u;
                ldmx4(ah[i], smAh + off);
                ldmx4(al[i], smAl + off);
            }
            #pragma unroll
            for (int j = 0; j < 4; j++) {
                const uint32_t off = (uint32_t)(bOff + j*8*GSTR + kt*16) * 2u;
                ldmx2(bh[j], smBh + off);
                ldmx2(bl[j], smBl + off);
            }
            #pragma unroll
            for (int i = 0; i < 4; i++)
                #pragma unroll
                for (int j = 0; j < 4; j++) {
                    mma_bf16(acc[i][j], ah[i], bh[j]);
                    mma_bf16(acc[i][j], ah[i], bl[j]);
                    mma_bf16(acc[i][j], al[i], bh[j]);
                }
        }
        __syncthreads();
    }

    #pragma unroll
    for (int i = 0; i < 4; i++) {
        const int m = m0 + wm*64 + i*16 + gid;
        #pragma unroll
        for (int j = 0; j < 4; j++) {
            const int n = n0 + wn*32 + j*8 + tig*2;
            const float2 bv = *(const float2*)&bias[n];
            float2 o0, o1;
            o0.x = acc[i][j][0] + bv.x; o0.y = acc[i][j][1] + bv.y;
            o1.x = acc[i][j][2] + bv.x; o1.y = acc[i][j][3] + bv.y;
            if (H) {
                uint32_t hp, lp;
                split2(o0.x, o0.y, hp, lp);
                *(uint32_t*)(H + (size_t)m*EMD + n) = hp;
                *(uint32_t*)(L + (size_t)m*EMD + n) = lp;
                split2(o1.x, o1.y, hp, lp);
                *(uint32_t*)(H + (size_t)(m+8)*EMD + n) = hp;
                *(uint32_t*)(L + (size_t)(m+8)*EMD + n) = lp;
            } else {
                *(float2*)(C + (size_t)m*EMD + n)     = o0;
                *(float2*)(C + (size_t)(m+8)*EMD + n) = o1;
            }
        }
    }
}

// ---------------------------------------------------------------------------
// Sum the 4 split-K partial O buffers -> split-bf16 hi/lo planes.
// ---------------------------------------------------------------------------
__global__ __launch_bounds__(256)
void presum_o()
{
    const int N = MROWS * EMD / 4;
    const float4* o0 = (const float4*)g_O0;
    const float4* o1 = (const float4*)g_O1;
    const float4* o2 = (const float4*)g_O2;
    const float4* o3 = (const float4*)g_O3;
    for (int i = blockIdx.x*256 + threadIdx.x; i < N; i += gridDim.x*256) {
        float4 a = o0[i];
        const float4 b = o1[i], c = o2[i], d = o3[i];
        a.x = (a.x + b.x) + (c.x + d.x);
        a.y = (a.y + b.y) + (c.y + d.y);
        a.z = (a.z + b.z) + (c.z + d.z);
        a.w = (a.w + b.w) + (c.w + d.w);
        uint32_t h0, l0, h1, l1;
        split2(a.x, a.y, h0, l0);
        split2(a.z, a.w, h1, l1);
        uint2 hh; hh.x = h0; hh.y = h1;
        uint2 ll; ll.x = l0; ll.y = l1;
        *(uint2*)(g_Ohi + (size_t)i*4) = hh;
        *(uint2*)(g_Olo + (size_t)i*4) = ll;
    }
}

// ---------------------------------------------------------------------------
// Fused attention, softmax over HEADS axis. Split-K4, TQ=32.
// E  = Q K^T  split-bf16 m16n8k16; AV = A V split-bf16 with A-frags built in
// registers from the E C-frags, scaled by cross-head 1/denom; V B-frags via
// ldmatrix.x2.trans.  NEW: K/V tiles filled with cp.async in two groups —
// K waited before E, V waited only before AV (fill overlaps E/exp/denom).
// ---------------------------------------------------------------------------
__global__ __launch_bounds__(256)
void attn_kernel()
{
    extern __shared__ char smx[];
    uint16_t* Qhi = (uint16_t*)(smx);            // 49664
    uint16_t* Qlo = (uint16_t*)(smx + 49664);    // 49664
    uint16_t* Khi = (uint16_t*)(smx + 99328);    // 24832
    uint16_t* Klo = (uint16_t*)(smx + 124160);   // 24832
    uint16_t* Vhi = (uint16_t*)(smx + 148992);   // 24832
    uint16_t* Vlo = (uint16_t*)(smx + 173824);   // 24832
    float*    Es  = (float*)   (smx + 198656);   // 18432
    float*    Dinv= (float*)   (smx + 217088);   // 2304

    const int b    = blockIdx.y;
    const int q0   = blockIdx.x * TQ;
    const int kh   = blockIdx.z;
    const int tid  = threadIdx.x;
    const int warp = tid >> 5;              // head
    const int lane = tid & 31;
    const int gid  = lane >> 2;             // 0..7
    const int tig  = lane & 3;              // 0..3
    const int hb   = warp * HDIM;           // head col base

    const uint32_t sKhi = smem_u32(Khi), sKlo = smem_u32(Klo);
    const uint32_t sVhi = smem_u32(Vhi), sVlo = smem_u32(Vlo);

    // ---- Q planes -> smem (once per CTA) ----
    for (int j = tid; j < TQ*(EMD/8); j += 256) {
        const int r  = j / (EMD/8);
        const int c8 = (j % (EMD/8)) * 8;
        const size_t g = (size_t)(b*SEQ + q0 + r)*EMD + c8;
        *(uint4*)(Qhi + (size_t)r*QSTR + c8) = *(const uint4*)(g_Qhi + g);
        *(uint4*)(Qlo + (size_t)r*QSTR + c8) = *(const uint4*)(g_Qlo + g);
    }

    float Oacc[2][12][4];
    #pragma unroll
    for (int i = 0; i < 2; i++)
        #pragma unroll
        for (int jj = 0; jj < 12; jj++)
            #pragma unroll
            for (int r = 0; r < 4; r++) Oacc[i][jj][r] = 0.f;

    const uint32_t vhiA = sVhi + (uint32_t)((lane & 15) * QSTR + hb) * 2u;
    const uint32_t vloA = sVlo + (uint32_t)((lane & 15) * QSTR + hb) * 2u;

    const int kbeg = kh * KCHUNK;
    for (int k0 = kbeg; k0 < kbeg + KCHUNK; k0 += TK) {
        // ---- issue K fill (group), then V fill (group) via cp.async ----
        #pragma unroll
        for (int jj = 0; jj < 6; jj++) {
            const int j  = tid + jj*256;
            const int r  = j / (EMD/8);
            const int c8 = (j % (EMD/8)) * 8;
            const size_t g  = (size_t)(b*SEQ + k0 + r)*EMD + c8;
            const uint32_t so = (uint32_t)(r*QSTR + c8) * 2u;
            cpa16(sKhi + so, g_Khi + g);
            cpa16(sKlo + so, g_Klo + g);
        }
        CP_COMMIT();
        #pragma unroll
        for (int jj = 0; jj < 6; jj++) {
            const int j  = tid + jj*256;
            const int r  = j / (EMD/8);
            const int c8 = (j % (EMD/8)) * 8;
            const size_t g  = (size_t)(b*SEQ + k0 + r)*EMD + c8;
            const uint32_t so = (uint32_t)(r*QSTR + c8) * 2u;
            cpa16(sVhi + so, g_Vhi + g);
            cpa16(sVlo + so, g_Vlo + g);
        }
        CP_COMMIT();
        CP_WAIT(1);            // K arrived (V may still be in flight)
        __syncthreads();       // (b) K visible to all; Q visible (iter 0)

        // ---- E = Q K^T : 32x16 per warp, split-bf16, 72 MMAs ----
        float eacc[2][2][4];
        #pragma unroll
        for (int i = 0; i < 2; i++)
            #pragma unroll
            for (int j = 0; j < 2; j++)
                #pragma unroll
                for (int r = 0; r < 4; r++) eacc[i][j][r] = 0.f;

        #pragma unroll
        for (int s = 0; s < 6; s++) {
            const int cA = hb + s*16 + tig*2;
            uint32_t ah[2][4], al[2][4], bh[2][2], bl[2][2];
            #pragma unroll
            for (int i = 0; i < 2; i++) {
                const size_t ro = (size_t)(i*16 + gid)*QSTR + cA;
                const uint16_t* ph = Qhi + ro;
                ah[i][0] = *(const uint32_t*)(ph);
                ah[i][1] = *(const uint32_t*)(ph + (size_t)8*QSTR);
                ah[i][2] = *(const uint32_t*)(ph + 8);
                ah[i][3] = *(const uint32_t*)(ph + (size_t)8*QSTR + 8);
                const uint16_t* pl = Qlo + ro;
                al[i][0] = *(const uint32_t*)(pl);
                al[i][1] = *(const uint32_t*)(pl + (size_t)8*QSTR);
                al[i][2] = *(const uint32_t*)(pl + 8);
                al[i][3] = *(const uint32_t*)(pl + (size_t)8*QSTR + 8);
            }
            #pragma unroll
            for (int j = 0; j < 2; j++) {
                const size_t ro = (size_t)(j*8 + gid)*QSTR + cA;
                const uint16_t* ph = Khi + ro;
                bh[j][0] = *(const uint32_t*)(ph);
                bh[j][1] = *(const uint32_t*)(ph + 8);
                const uint16_t* pl = Klo + ro;
                bl[j][0] = *(const uint32_t*)(pl);
                bl[j][1] = *(const uint32_t*)(pl + 8);
            }
            #pragma unroll
            for (int i = 0; i < 2; i++)
                #pragma unroll
                for (int j = 0; j < 2; j++) {
                    mma_bf16(eacc[i][j], ah[i], bh[j]);
                    mma_bf16(eacc[i][j], ah[i], bl[j]);
                    mma_bf16(eacc[i][j], al[i], bh[j]);
                }
        }

        // ---- exp in registers; copies to Es for the denominator ----
        float ex[2][2][4];
        #pragma unroll
        for (int i = 0; i < 2; i++) {
            const int r0 = warp*TQ + i*16 + gid;
            #pragma unroll
            for (int j = 0; j < 2; j++) {
                const int c0 = j*8 + tig*2;
                ex[i][j][0] = __expf(eacc[i][j][0]);
                ex[i][j][1] = __expf(eacc[i][j][1]);
                ex[i][j][2] = __expf(eacc[i][j][2]);
                ex[i][j][3] = __expf(eacc[i][j][3]);
                float2 e0; e0.x = ex[i][j][0]; e0.y = ex[i][j][1];
                float2 e1; e1.x = ex[i][j][2]; e1.y = ex[i][j][3];
                *(float2*)&Es[(r0    )*ESTR + c0] = e0;
                *(float2*)&Es[(r0 + 8)*ESTR + c0] = e1;
            }
        }
        __syncthreads();       // (c) Es visible; all E reads of K done

        // ---- cross-head denominator -> Dinv ----
        #pragma unroll
        for (int pp = 0; pp < 2; pp++) {
            const int p = tid*2 + pp;
            const int q = p >> 4;
            const int k = p & 15;
            float s = 0.f;
            #pragma unroll
            for (int h = 0; h < HEADS; h++) s += Es[(h*TQ + q)*ESTR + k];
            Dinv[q*ESTR + k] = 1.0f / (s * SQRT_EMD);
        }
        CP_WAIT(0);            // V arrived
        __syncthreads();       // (d) Dinv + V visible

        // ---- A-fragments in registers: a = exp * inv, split-bf16 ----
        uint32_t Ah[2][4], Al[2][4];
        #pragma unroll
        for (int i = 0; i < 2; i++) {
            const int r0 = (i*16 + gid)*ESTR;
            const int r1 = (i*16 + gid + 8)*ESTR;
            const float2 i00 = *(const float2*)&Dinv[r0 + tig*2];
            const float2 i10 = *(const float2*)&Dinv[r1 + tig*2];
            const float2 i01 = *(const float2*)&Dinv[r0 + tig*2 + 8];
            const float2 i11 = *(const float2*)&Dinv[r1 + tig*2 + 8];
            split2(ex[i][0][0]*i00.x, ex[i][0][1]*i00.y, Ah[i][0], Al[i][0]);
            split2(ex[i][0][2]*i10.x, ex[i][0][3]*i10.y, Ah[i][1], Al[i][1]);
            split2(ex[i][1][0]*i01.x, ex[i][1][1]*i01.y, Ah[i][2], Al[i][2]);
            split2(ex[i][1][2]*i11.x, ex[i][1][3]*i11.y, Ah[i][3], Al[i][3]);
        }

        // ---- O += A @ V : V B-frags via ldmatrix.trans, 72 MMAs ----
        #pragma unroll
        for (int jj = 0; jj < 12; jj++) {
            uint32_t bh[2], bl[2];
            ldmx2t(bh[0], bh[1], vhiA + jj*16);
            ldmx2t(bl[0], bl[1], vloA + jj*16);
            #pragma unroll
            for (int i = 0; i < 2; i++) {
                mma_bf16(Oacc[i][jj], Ah[i], bh);
                mma_bf16(Oacc[i][jj], Ah[i], bl);
                mma_bf16(Oacc[i][jj], Al[i], bh);
            }
        }
        __syncthreads();       // (a) K/V/Es reads done before next iter's fills
    }

    // ---- write partial O in [M, 768] layout ----
    float* Obase = (kh == 0) ? g_O0 : (kh == 1) ? g_O1 : (kh == 2) ? g_O2 : g_O3;
    #pragma unroll
    for (int i = 0; i < 2; i++) {
        const size_t r0 = (size_t)(b*SEQ + q0 + i*16 + gid);
        #pragma unroll
        for (int jj = 0; jj < 12; jj++) {
            const int n = hb + jj*8 + tig*2;
            float2 o0; o0.x = Oacc[i][jj][0]; o0.y = Oacc[i][jj][1];
            float2 o1; o1.x = Oacc[i][jj][2]; o1.y = Oacc[i][jj][3];
            *(float2*)(Obase + r0*EMD + n)       = o0;
            *(float2*)(Obase + (r0+8)*EMD + n)   = o1;
        }
    }
}

// ---------------------------------------------------------------------------
extern "C" void kernel_launch(void* const* d_in, const int* in_sizes, int n_in,
                              void* d_out, int out_size)
{
    const float* x  = (const float*)d_in[0];
    const float* Wq = (const float*)d_in[1];
    const float* bq = (const float*)d_in[2];
    const float* Wk = (const float*)d_in[3];
    const float* bk = (const float*)d_in[4];
    const float* Wv = (const float*)d_in[5];
    const float* bv = (const float*)d_in[6];
    const float* Wo = (const float*)d_in[7];
    const float* bo = (const float*)d_in[8];
    float* out = (float*)d_out;

    uint16_t *Qh, *Ql, *Kh, *Kl, *Vh, *Vl, *xh, *xl, *Oh, *Ol;
    uint16_t *wqh, *wql, *wkh, *wkl, *wvh, *wvl, *woh, *wol;
    cudaGetSymbolAddress((void**)&Qh,  g_Qhi);
    cudaGetSymbolAddress((void**)&Ql,  g_Qlo);
    cudaGetSymbolAddress((void**)&Kh,  g_Khi);
    cudaGetSymbolAddress((void**)&Kl,  g_Klo);
    cudaGetSymbolAddress((void**)&Vh,  g_Vhi);
    cudaGetSymbolAddress((void**)&Vl,  g_Vlo);
    cudaGetSymbolAddress((void**)&xh,  g_xhi);
    cudaGetSymbolAddress((void**)&xl,  g_xlo);
    cudaGetSymbolAddress((void**)&Oh,  g_Ohi);
    cudaGetSymbolAddress((void**)&Ol,  g_Olo);
    cudaGetSymbolAddress((void**)&wqh, g_Wqh);
    cudaGetSymbolAddress((void**)&wql, g_Wql);
    cudaGetSymbolAddress((void**)&wkh, g_Wkh);
    cudaGetSymbolAddress((void**)&wkl, g_Wkl);
    cudaGetSymbolAddress((void**)&wvh, g_Wvh);
    cudaGetSymbolAddress((void**)&wvl, g_Wvl);
    cudaGetSymbolAddress((void**)&woh, g_Woh);
    cudaGetSymbolAddress((void**)&wol, g_Wol);

    const int smem_bytes = 219392;
    cudaFuncSetAttribute(attn_kernel, cudaFuncAttributeMaxDynamicSharedMemorySize, smem_bytes);

    // 0) Pre-split inputs into global bf16 hi/lo planes
    split_f32<<<1024, 256>>>(x,  xh,  xl,  MROWS*EMD/4);
    split_f32<<<288,  256>>>(Wq, wqh, wql, EMD*EMD/4);
    split_f32<<<288,  256>>>(Wk, wkh, wkl, EMD*EMD/4);
    split_f32<<<288,  256>>>(Wv, wvh, wvl, EMD*EMD/4);
    split_f32<<<288,  256>>>(Wo, woh, wol, EMD*EMD/4);

    // 1) Fused QKV projections (split-bf16 GEMM from planes) -> Q/K/V planes
    gemm_bf16<<<dim3(MROWS/128, EMD/128, 3), 256>>>(
        xh, xl,
        wqh, wql, bq, (float*)0, Qh, Ql,
        wkh, wkl, bk, (float*)0, Kh, Kl,
        wvh, wvl, bv, (float*)0, Vh, Vl);

    // 2) Fused head-axis-softmax attention, split-K4, cp.async-pipelined
    attn_kernel<<<dim3(SEQ/TQ, BATCH, KSPLIT), 256, smem_bytes>>>();

    // 3) Sum split-K partials -> O hi/lo planes
    presum_o<<<2048, 256>>>();

    // 4) Output projection (split-bf16 GEMM, fp32 out) -> d_out
    gemm_bf16<<<dim3(MROWS/128, EMD/128, 1), 256>>>(
        Oh, Ol,
        woh, wol, bo, out, (uint16_t*)0, (uint16_t*)0,
        woh, wol, bo, out, (uint16_t*)0, (uint16_t*)0,
        woh, wol, bo, out, (uint16_t*)0, (uint16_t*)0);
}

// round 17
// speedup vs baseline: 1.4309x; 1.0714x over previous
#include <cuda_runtime.h>
#include <math.h>
#include <stdint.h>

#define BATCH 4
#define SEQ   2048
#define EMD   768
#define HEADS 8
#define HDIM  96
#define MROWS (BATCH*SEQ)

#define TQ 32
#define TK 16
#define KSPLIT 4
#define KCHUNK (SEQ/KSPLIT)
#define QSTR 776           // bf16 elements per smem row (attention)
#define ESTR 18
#define GSTR 40            // bf16 elements per smem row (GEMM BK=32 + pad)
#define SQRT_EMD 27.712812921102035f

// C(16x8,f32) += A(16x16,bf16,row) * B(16x8,bf16,col)
__device__ __forceinline__ void mma_bf16(float* d, const uint32_t* a, const uint32_t* b) {
    asm volatile(
        "mma.sync.aligned.m16n8k16.row.col.f32.bf16.bf16.f32 "
        "{%0,%1,%2,%3}, {%4,%5,%6,%7}, {%8,%9}, {%0,%1,%2,%3};"
        : "+f"(d[0]), "+f"(d[1]), "+f"(d[2]), "+f"(d[3])
        : "r"(a[0]), "r"(a[1]), "r"(a[2]), "r"(a[3]), "r"(b[0]), "r"(b[1]));
}
__device__ __forceinline__ uint32_t bfx2(float lo, float hi) {
    uint32_t r; asm("cvt.rn.bf16x2.f32 %0, %1, %2;" : "=r"(r) : "f"(hi), "f"(lo)); return r;
}
// split (x,y) into hi-pair (bf16 rn) and lo-pair (residual as bf16); lo half = x
__device__ __forceinline__ void split2(float x, float y, uint32_t& hp, uint32_t& lp) {
    const uint32_t bx = __float_as_uint(x), by = __float_as_uint(y);
    const uint32_t rx = (bx + 0x7FFFu + ((bx >> 16) & 1u)) & 0xFFFF0000u;
    const uint32_t ry = (by + 0x7FFFu + ((by >> 16) & 1u)) & 0xFFFF0000u;
    hp = ry | (rx >> 16);
    lp = bfx2(x - __uint_as_float(rx), y - __uint_as_float(ry));
}
__device__ __forceinline__ uint32_t smem_u32(const void* p) {
    uint32_t a;
    asm("{ .reg .u64 t; cvta.to.shared.u64 t, %1; cvt.u32.u64 %0, t; }" : "=r"(a) : "l"(p));
    return a;
}
__device__ __forceinline__ void ldmx4(uint32_t* r, uint32_t addr) {
    asm volatile("ldmatrix.sync.aligned.m8n8.x4.shared.b16 {%0,%1,%2,%3}, [%4];"
                 : "=r"(r[0]), "=r"(r[1]), "=r"(r[2]), "=r"(r[3]) : "r"(addr));
}
__device__ __forceinline__ void ldmx2(uint32_t* r, uint32_t addr) {
    asm volatile("ldmatrix.sync.aligned.m8n8.x2.shared.b16 {%0,%1}, [%2];"
                 : "=r"(r[0]), "=r"(r[1]) : "r"(addr));
}
__device__ __forceinline__ void ldmx2t(uint32_t& b0, uint32_t& b1, uint32_t addr) {
    asm volatile("ldmatrix.sync.aligned.m8n8.x2.trans.shared.b16 {%0,%1}, [%2];"
                 : "=r"(b0), "=r"(b1) : "r"(addr));
}
__device__ __forceinline__ void cpa16(uint32_t saddr, const void* gaddr) {
    asm volatile("cp.async.cg.shared.global [%0], [%1], 16;" :: "r"(saddr), "l"(gaddr) : "memory");
}
#define CP_COMMIT() asm volatile("cp.async.commit_group;" ::: "memory")
#define CP_WAIT(n)  asm volatile("cp.async.wait_group %0;" :: "n"(n) : "memory")

// Scratch (allocation-free rule: __device__ globals)
__device__ uint16_t g_Qhi[MROWS*EMD], g_Qlo[MROWS*EMD];
__device__ uint16_t g_Khi[MROWS*EMD], g_Klo[MROWS*EMD];
__device__ uint16_t g_Vhi[MROWS*EMD], g_Vlo[MROWS*EMD];
__device__ uint16_t g_xhi[MROWS*EMD], g_xlo[MROWS*EMD];
__device__ uint16_t g_Ohi[MROWS*EMD], g_Olo[MROWS*EMD];
__device__ uint16_t g_Wqh[EMD*EMD], g_Wql[EMD*EMD];
__device__ uint16_t g_Wkh[EMD*EMD], g_Wkl[EMD*EMD];
__device__ uint16_t g_Wvh[EMD*EMD], g_Wvl[EMD*EMD];
__device__ uint16_t g_Woh[EMD*EMD], g_Wol[EMD*EMD];
__device__ float g_O0[MROWS*EMD];
__device__ float g_O1[MROWS*EMD];
__device__ float g_O2[MROWS*EMD];
__device__ float g_O3[MROWS*EMD];

// ---------------------------------------------------------------------------
// Elementwise split: fp32 -> bf16 hi/lo planes (float4 grid-stride).
// ---------------------------------------------------------------------------
__global__ __launch_bounds__(256)
void split_f32(const float* __restrict__ src, uint16_t* __restrict__ hi,
               uint16_t* __restrict__ lo, int n4)
{
    for (int i = blockIdx.x*256 + threadIdx.x; i < n4; i += gridDim.x*256) {
        const float4 v = ((const float4*)src)[i];
        uint32_t h0, l0, h1, l1;
        split2(v.x, v.y, h0, l0);
        split2(v.z, v.w, h1, l1);
        uint2 hh; hh.x = h0; hh.y = h1;
        uint2 ll; ll.x = l0; ll.y = l1;
        *(uint2*)(hi + (size_t)i*4) = hh;
        *(uint2*)(lo + (size_t)i*4) = ll;
    }
}

// ---------------------------------------------------------------------------
// split-bf16 NT GEMM from PRE-SPLIT hi/lo planes (unchanged from R16).
// ---------------------------------------------------------------------------
__global__ __launch_bounds__(256, 2)
void gemm_bf16(const uint16_t* __restrict__ Ah_g, const uint16_t* __restrict__ Al_g,
               const uint16_t* __restrict__ Wh0, const uint16_t* __restrict__ Wl0,
               const float* __restrict__ bv0, float* __restrict__ C0,
               uint16_t* __restrict__ H0, uint16_t* __restrict__ L0,
               const uint16_t* __restrict__ Wh1, const uint16_t* __restrict__ Wl1,
               const float* __restrict__ bv1, float* __restrict__ C1,
               uint16_t* __restrict__ H1, uint16_t* __restrict__ L1,
               const uint16_t* __restrict__ Wh2, const uint16_t* __restrict__ Wl2,
               const float* __restrict__ bv2, float* __restrict__ C2,
               uint16_t* __restrict__ H2, uint16_t* __restrict__ L2)
{
    const uint16_t* Wh = Wh0;
    const uint16_t* Wl = Wl0;
    const float* bias  = bv0;
    float*       C     = C0;
    uint16_t*    H     = H0;
    uint16_t*    L     = L0;
    if (blockIdx.z == 1) { Wh = Wh1; Wl = Wl1; bias = bv1; C = C1; H = H1; L = L1; }
    if (blockIdx.z == 2) { Wh = Wh2; Wl = Wl2; bias = bv2; C = C2; H = H2; L = L2; }

    __shared__ __align__(16) uint16_t Ahi[128*GSTR], Alo[128*GSTR];
    __shared__ __align__(16) uint16_t Bhi[128*GSTR], Blo[128*GSTR];

    const int tid  = threadIdx.x;
    const int w    = tid >> 5;
    const int lane = tid & 31;
    const int wm   = w & 1;
    const int wn   = w >> 1;
    const int gid  = lane >> 2;
    const int tig  = lane & 3;
    const int m0   = blockIdx.x * 128;
    const int n0   = blockIdx.y * 128;

    const int lr = tid >> 1;
    const int lc = (tid & 1) * 16;

    const uint16_t* pAh = Ah_g + (size_t)(m0 + lr) * EMD + lc;
    const uint16_t* pAl = Al_g + (size_t)(m0 + lr) * EMD + lc;
    const uint16_t* pWh = Wh   + (size_t)(n0 + lr) * EMD + lc;
    const uint16_t* pWl = Wl   + (size_t)(n0 + lr) * EMD + lc;

    const int l15  = lane & 15;
    const int aOff = (wm*64 + l15) * GSTR + ((lane >> 4) << 3);
    const int bOff = (wn*32 + (l15 & 7)) * GSTR + ((l15 >> 3) << 3);

    const uint32_t smAh = smem_u32(Ahi), smAl = smem_u32(Alo);
    const uint32_t smBh = smem_u32(Bhi), smBl = smem_u32(Blo);

    float acc[4][4][4];
    #pragma unroll
    for (int i = 0; i < 4; i++)
        #pragma unroll
        for (int j = 0; j < 4; j++)
            #pragma unroll
            for (int r = 0; r < 4; r++) acc[i][j][r] = 0.f;

    for (int k0 = 0; k0 < EMD; k0 += 32) {
        *(uint4*)&Ahi[lr*GSTR+lc]   = *(const uint4*)(pAh + k0);
        *(uint4*)&Ahi[lr*GSTR+lc+8] = *(const uint4*)(pAh + k0 + 8);
        *(uint4*)&Alo[lr*GSTR+lc]   = *(const uint4*)(pAl + k0);
        *(uint4*)&Alo[lr*GSTR+lc+8] = *(const uint4*)(pAl + k0 + 8);
        *(uint4*)&Bhi[lr*GSTR+lc]   = *(const uint4*)(pWh + k0);
        *(uint4*)&Bhi[lr*GSTR+lc+8] = *(const uint4*)(pWh + k0 + 8);
        *(uint4*)&Blo[lr*GSTR+lc]   = *(const uint4*)(pWl + k0);
        *(uint4*)&Blo[lr*GSTR+lc+8] = *(const uint4*)(pWl + k0 + 8);
        __syncthreads();

        #pragma unroll
        for (int kt = 0; kt < 2; kt++) {
            uint32_t ah[4][4], al[4][4], bh[4][2], bl[4][2];
            #pragma unroll
            for (int i = 0; i < 4; i++) {
                const uint32_t off = (uint32_t)(aOff + i*16*GSTR + kt*16) * 2u;
                ldmx4(ah[i], smAh + off);
                ldmx4(al[i], smAl + off);
            }
            #pragma unroll
            for (int j = 0; j < 4; j++) {
                const uint32_t off = (uint32_t)(bOff + j*8*GSTR + kt*16) * 2u;
                ldmx2(bh[j], smBh + off);
                ldmx2(bl[j], smBl + off);
            }
            #pragma unroll
            for (int i = 0; i < 4; i++)
                #pragma unroll
                for (int j = 0; j < 4; j++) {
                    mma_bf16(acc[i][j], ah[i], bh[j]);
                    mma_bf16(acc[i][j], ah[i], bl[j]);
                    mma_bf16(acc[i][j], al[i], bh[j]);
                }
        }
        __syncthreads();
    }

    #pragma unroll
    for (int i = 0; i < 4; i++) {
        const int m = m0 + wm*64 + i*16 + gid;
        #pragma unroll
        for (int j = 0; j < 4; j++) {
            const int n = n0 + wn*32 + j*8 + tig*2;
            const float2 bv = *(const float2*)&bias[n];
            float2 o0, o1;
            o0.x = acc[i][j][0] + bv.x; o0.y = acc[i][j][1] + bv.y;
            o1.x = acc[i][j][2] + bv.x; o1.y = acc[i][j][3] + bv.y;
            if (H) {
                uint32_t hp, lp;
                split2(o0.x, o0.y, hp, lp);
                *(uint32_t*)(H + (size_t)m*EMD + n) = hp;
                *(uint32_t*)(L + (size_t)m*EMD + n) = lp;
                split2(o1.x, o1.y, hp, lp);
                *(uint32_t*)(H + (size_t)(m+8)*EMD + n) = hp;
                *(uint32_t*)(L + (size_t)(m+8)*EMD + n) = lp;
            } else {
                *(float2*)(C + (size_t)m*EMD + n)     = o0;
                *(float2*)(C + (size_t)(m+8)*EMD + n) = o1;
            }
        }
    }
}

// ---------------------------------------------------------------------------
// Sum the 4 split-K partial O buffers -> split-bf16 hi/lo planes.
// ---------------------------------------------------------------------------
__global__ __launch_bounds__(256)
void presum_o()
{
    const int N = MROWS * EMD / 4;
    const float4* o0 = (const float4*)g_O0;
    const float4* o1 = (const float4*)g_O1;
    const float4* o2 = (const float4*)g_O2;
    const float4* o3 = (const float4*)g_O3;
    for (int i = blockIdx.x*256 + threadIdx.x; i < N; i += gridDim.x*256) {
        float4 a = o0[i];
        const float4 b = o1[i], c = o2[i], d = o3[i];
        a.x = (a.x + b.x) + (c.x + d.x);
        a.y = (a.y + b.y) + (c.y + d.y);
        a.z = (a.z + b.z) + (c.z + d.z);
        a.w = (a.w + b.w) + (c.w + d.w);
        uint32_t h0, l0, h1, l1;
        split2(a.x, a.y, h0, l0);
        split2(a.z, a.w, h1, l1);
        uint2 hh; hh.x = h0; hh.y = h1;
        uint2 ll; ll.x = l0; ll.y = l1;
        *(uint2*)(g_Ohi + (size_t)i*4) = hh;
        *(uint2*)(g_Olo + (size_t)i*4) = ll;
    }
}

// ---------------------------------------------------------------------------
// Fused attention, softmax over HEADS axis. Split-K4, TQ=32.
// NEW this round: (1) distance-1 cp.async pipeline in-place — K[n+1] issued
// after the post-E barrier, V[n+1] after the post-AV barrier; every wait is
// wait_group 1 and fill latency hides under compute. (2) E-phase fragments
// via ldmatrix.x4 (36 LDSM/warp/iter vs 144 LDS.32).
// ---------------------------------------------------------------------------
__global__ __launch_bounds__(256)
void attn_kernel()
{
    extern __shared__ char smx[];
    uint16_t* Qhi = (uint16_t*)(smx);            // 49664
    uint16_t* Qlo = (uint16_t*)(smx + 49664);    // 49664
    uint16_t* Khi = (uint16_t*)(smx + 99328);    // 24832
    uint16_t* Klo = (uint16_t*)(smx + 124160);   // 24832
    uint16_t* Vhi = (uint16_t*)(smx + 148992);   // 24832
    uint16_t* Vlo = (uint16_t*)(smx + 173824);   // 24832
    float*    Es  = (float*)   (smx + 198656);   // 18432
    float*    Dinv= (float*)   (smx + 217088);   // 2304

    const int b    = blockIdx.y;
    const int q0   = blockIdx.x * TQ;
    const int kh   = blockIdx.z;
    const int tid  = threadIdx.x;
    const int warp = tid >> 5;              // head
    const int lane = tid & 31;
    const int gid  = lane >> 2;             // 0..7
    const int tig  = lane & 3;              // 0..3
    const int hb   = warp * HDIM;           // head col base

    const uint32_t sKhi = smem_u32(Khi), sKlo = smem_u32(Klo);
    const uint32_t sVhi = smem_u32(Vhi), sVlo = smem_u32(Vlo);

    // ldmatrix lane-address bases (element units within a plane, x2 for bytes)
    const int l15 = lane & 15;
    const uint32_t qA_h = smem_u32(Qhi) + (uint32_t)(l15*QSTR + hb + ((lane >> 4) << 3)) * 2u;
    const uint32_t qA_l = smem_u32(Qlo) + (uint32_t)(l15*QSTR + hb + ((lane >> 4) << 3)) * 2u;
    const int kBrow = ((lane & 16) >> 1) + (lane & 7);   // 0..15
    const int kBcol = lane & 8;                          // 0 or 8
    const uint32_t kB_h = sKhi + (uint32_t)(kBrow*QSTR + hb + kBcol) * 2u;
    const uint32_t kB_l = sKlo + (uint32_t)(kBrow*QSTR + hb + kBcol) * 2u;
    const uint32_t vhiA = sVhi + (uint32_t)((lane & 15) * QSTR + hb) * 2u;
    const uint32_t vloA = sVlo + (uint32_t)((lane & 15) * QSTR + hb) * 2u;

    // ---- Q planes -> smem (once per CTA) ----
    for (int j = tid; j < TQ*(EMD/8); j += 256) {
        const int r  = j / (EMD/8);
        const int c8 = (j % (EMD/8)) * 8;
        const size_t g = (size_t)(b*SEQ + q0 + r)*EMD + c8;
        *(uint4*)(Qhi + (size_t)r*QSTR + c8) = *(const uint4*)(g_Qhi + g);
        *(uint4*)(Qlo + (size_t)r*QSTR + c8) = *(const uint4*)(g_Qlo + g);
    }

    float Oacc[2][12][4];
    #pragma unroll
    for (int i = 0; i < 2; i++)
        #pragma unroll
        for (int jj = 0; jj < 12; jj++)
            #pragma unroll
            for (int r = 0; r < 4; r++) Oacc[i][jj][r] = 0.f;

    const int kbeg = kh * KCHUNK;
    const int kend = kbeg + KCHUNK;

    // ---- prologue: issue K[kbeg] then V[kbeg] ----
    #pragma unroll
    for (int jj = 0; jj < 6; jj++) {
        const int j  = tid + jj*256;
        const int r  = j / (EMD/8);
        const int c8 = (j % (EMD/8)) * 8;
        const size_t g  = (size_t)(b*SEQ + kbeg + r)*EMD + c8;
        const uint32_t so = (uint32_t)(r*QSTR + c8) * 2u;
        cpa16(sKhi + so, g_Khi + g);
        cpa16(sKlo + so, g_Klo + g);
    }
    CP_COMMIT();
    #pragma unroll
    for (int jj = 0; jj < 6; jj++) {
        const int j  = tid + jj*256;
        const int r  = j / (EMD/8);
        const int c8 = (j % (EMD/8)) * 8;
        const size_t g  = (size_t)(b*SEQ + kbeg + r)*EMD + c8;
        const uint32_t so = (uint32_t)(r*QSTR + c8) * 2u;
        cpa16(sVhi + so, g_Vhi + g);
        cpa16(sVlo + so, g_Vlo + g);
    }
    CP_COMMIT();

    for (int k0 = kbeg; k0 < kend; k0 += TK) {
        CP_WAIT(1);            // K[n] landed (V[n] may be in flight)
        __syncthreads();       // (b) K visible to all; Q visible (iter 0)

        // ---- E = Q K^T : 32x16 per warp, split-bf16, ldmatrix frags ----
        float eacc[2][2][4];
        #pragma unroll
        for (int i = 0; i < 2; i++)
            #pragma unroll
            for (int j = 0; j < 2; j++)
                #pragma unroll
                for (int r = 0; r < 4; r++) eacc[i][j][r] = 0.f;

        #pragma unroll
        for (int s = 0; s < 6; s++) {
            const uint32_t sOff = (uint32_t)(s*16) * 2u;
            uint32_t ah[2][4], al[2][4], bh[4], bl[4];
            ldmx4(ah[0], qA_h + sOff);
            ldmx4(ah[1], qA_h + (uint32_t)(16*QSTR)*2u + sOff);
            ldmx4(al[0], qA_l + sOff);
            ldmx4(al[1], qA_l + (uint32_t)(16*QSTR)*2u + sOff);
            ldmx4(bh, kB_h + sOff);
            ldmx4(bl, kB_l + sOff);
            #pragma unroll
            for (int i = 0; i < 2; i++)
                #pragma unroll
                for (int j = 0; j < 2; j++) {
                    mma_bf16(eacc[i][j], ah[i], &bh[j*2]);
                    mma_bf16(eacc[i][j], ah[i], &bl[j*2]);
                    mma_bf16(eacc[i][j], al[i], &bh[j*2]);
                }
        }

        // ---- exp in registers; copies to Es for the denominator ----
        float ex[2][2][4];
        #pragma unroll
        for (int i = 0; i < 2; i++) {
            const int r0 = warp*TQ + i*16 + gid;
            #pragma unroll
            for (int j = 0; j < 2; j++) {
                const int c0 = j*8 + tig*2;
                ex[i][j][0] = __expf(eacc[i][j][0]);
                ex[i][j][1] = __expf(eacc[i][j][1]);
                ex[i][j][2] = __expf(eacc[i][j][2]);
                ex[i][j][3] = __expf(eacc[i][j][3]);
                float2 e0; e0.x = ex[i][j][0]; e0.y = ex[i][j][1];
                float2 e1; e1.x = ex[i][j][2]; e1.y = ex[i][j][3];
                *(float2*)&Es[(r0    )*ESTR + c0] = e0;
                *(float2*)&Es[(r0 + 8)*ESTR + c0] = e1;
            }
        }
        __syncthreads();       // (c) Es visible; ALL warps done reading K

        // ---- issue K[n+1] into the (now free) K buffers ----
        {
            int kn = k0 + TK;
            if (kn >= kend) kn = kbeg;   // harmless re-read on the last iter
            #pragma unroll
            for (int jj = 0; jj < 6; jj++) {
                const int j  = tid + jj*256;
                const int r  = j / (EMD/8);
                const int c8 = (j % (EMD/8)) * 8;
                const size_t g  = (size_t)(b*SEQ + kn + r)*EMD + c8;
                const uint32_t so = (uint32_t)(r*QSTR + c8) * 2u;
                cpa16(sKhi + so, g_Khi + g);
                cpa16(sKlo + so, g_Klo + g);
            }
            CP_COMMIT();
        }

        // ---- cross-head denominator -> Dinv ----
        #pragma unroll
        for (int pp = 0; pp < 2; pp++) {
            const int p = tid*2 + pp;
            const int q = p >> 4;
            const int k = p & 15;
            float s = 0.f;
            #pragma unroll
            for (int h = 0; h < HEADS; h++) s += Es[(h*TQ + q)*ESTR + k];
            Dinv[q*ESTR + k] = 1.0f / (s * SQRT_EMD);
        }
        CP_WAIT(1);            // V[n] landed (K[n+1] may be in flight)
        __syncthreads();       // (d) Dinv + V visible

        // ---- A-fragments in registers: a = exp * inv, split-bf16 ----
        uint32_t Ah[2][4], Al[2][4];
        #pragma unroll
        for (int i = 0; i < 2; i++) {
            const int r0 = (i*16 + gid)*ESTR;
            const int r1 = (i*16 + gid + 8)*ESTR;
            const float2 i00 = *(const float2*)&Dinv[r0 + tig*2];
            const float2 i10 = *(const float2*)&Dinv[r1 + tig*2];
            const float2 i01 = *(const float2*)&Dinv[r0 + tig*2 + 8];
            const float2 i11 = *(const float2*)&Dinv[r1 + tig*2 + 8];
            split2(ex[i][0][0]*i00.x, ex[i][0][1]*i00.y, Ah[i][0], Al[i][0]);
            split2(ex[i][0][2]*i10.x, ex[i][0][3]*i10.y, Ah[i][1], Al[i][1]);
            split2(ex[i][1][0]*i01.x, ex[i][1][1]*i01.y, Ah[i][2], Al[i][2]);
            split2(ex[i][1][2]*i11.x, ex[i][1][3]*i11.y, Ah[i][3], Al[i][3]);
        }

        // ---- O += A @ V : V B-frags via ldmatrix.trans, 72 MMAs ----
        #pragma unroll
        for (int jj = 0; jj < 12; jj++) {
            uint32_t bh[2], bl[2];
            ldmx2t(bh[0], bh[1], vhiA + jj*16);
            ldmx2t(bl[0], bl[1], vloA + jj*16);
            #pragma unroll
            for (int i = 0; i < 2; i++) {
                mma_bf16(Oacc[i][jj], Ah[i], bh);
                mma_bf16(Oacc[i][jj], Ah[i], bl);
                mma_bf16(Oacc[i][jj], Al[i], bh);
            }
        }
        __syncthreads();       // (a) ALL warps done reading V/Es

        // ---- issue V[n+1] into the (now free) V buffers ----
        {
            int kn = k0 + TK;
            if (kn >= kend) kn = kbeg;
            #pragma unroll
            for (int jj = 0; jj < 6; jj++) {
                const int j  = tid + jj*256;
                const int r  = j / (EMD/8);
                const int c8 = (j % (EMD/8)) * 8;
                const size_t g  = (size_t)(b*SEQ + kn + r)*EMD + c8;
                const uint32_t so = (uint32_t)(r*QSTR + c8) * 2u;
                cpa16(sVhi + so, g_Vhi + g);
                cpa16(sVlo + so, g_Vlo + g);
            }
            CP_COMMIT();
        }
    }
    CP_WAIT(0);   // drain trailing fills before exit

    // ---- write partial O in [M, 768] layout ----
    float* Obase = (kh == 0) ? g_O0 : (kh == 1) ? g_O1 : (kh == 2) ? g_O2 : g_O3;
    #pragma unroll
    for (int i = 0; i < 2; i++) {
        const size_t r0 = (size_t)(b*SEQ + q0 + i*16 + gid);
        #pragma unroll
        for (int jj = 0; jj < 12; jj++) {
            const int n = hb + jj*8 + tig*2;
            float2 o0; o0.x = Oacc[i][jj][0]; o0.y = Oacc[i][jj][1];
            float2 o1; o1.x = Oacc[i][jj][2]; o1.y = Oacc[i][jj][3];
            *(float2*)(Obase + r0*EMD + n)       = o0;
            *(float2*)(Obase + (r0+8)*EMD + n)   = o1;
        }
    }
}

// ---------------------------------------------------------------------------
extern "C" void kernel_launch(void* const* d_in, const int* in_sizes, int n_in,
                              void* d_out, int out_size)
{
    const float* x  = (const float*)d_in[0];
    const float* Wq = (const float*)d_in[1];
    const float* bq = (const float*)d_in[2];
    const float* Wk = (const float*)d_in[3];
    const float* bk = (const float*)d_in[4];
    const float* Wv = (const float*)d_in[5];
    const float* bv = (const float*)d_in[6];
    const float* Wo = (const float*)d_in[7];
    const float* bo = (const float*)d_in[8];
    float* out = (float*)d_out;

    uint16_t *Qh, *Ql, *Kh, *Kl, *Vh, *Vl, *xh, *xl, *Oh, *Ol;
    uint16_t *wqh, *wql, *wkh, *wkl, *wvh, *wvl, *woh, *wol;
    cudaGetSymbolAddress((void**)&Qh,  g_Qhi);
    cudaGetSymbolAddress((void**)&Ql,  g_Qlo);
    cudaGetSymbolAddress((void**)&Kh,  g_Khi);
    cudaGetSymbolAddress((void**)&Kl,  g_Klo);
    cudaGetSymbolAddress((void**)&Vh,  g_Vhi);
    cudaGetSymbolAddress((void**)&Vl,  g_Vlo);
    cudaGetSymbolAddress((void**)&xh,  g_xhi);
    cudaGetSymbolAddress((void**)&xl,  g_xlo);
    cudaGetSymbolAddress((void**)&Oh,  g_Ohi);
    cudaGetSymbolAddress((void**)&Ol,  g_Olo);
    cudaGetSymbolAddress((void**)&wqh, g_Wqh);
    cudaGetSymbolAddress((void**)&wql, g_Wql);
    cudaGetSymbolAddress((void**)&wkh, g_Wkh);
    cudaGetSymbolAddress((void**)&wkl, g_Wkl);
    cudaGetSymbolAddress((void**)&wvh, g_Wvh);
    cudaGetSymbolAddress((void**)&wvl, g_Wvl);
    cudaGetSymbolAddress((void**)&woh, g_Woh);
    cudaGetSymbolAddress((void**)&wol, g_Wol);

    const int smem_bytes = 219392;
    cudaFuncSetAttribute(attn_kernel, cudaFuncAttributeMaxDynamicSharedMemorySize, smem_bytes);

    // 0) Pre-split inputs into global bf16 hi/lo planes
    split_f32<<<1024, 256>>>(x,  xh,  xl,  MROWS*EMD/4);
    split_f32<<<288,  256>>>(Wq, wqh, wql, EMD*EMD/4);
    split_f32<<<288,  256>>>(Wk, wkh, wkl, EMD*EMD/4);
    split_f32<<<288,  256>>>(Wv, wvh, wvl, EMD*EMD/4);
    split_f32<<<288,  256>>>(Wo, woh, wol, EMD*EMD/4);

    // 1) Fused QKV projections (split-bf16 GEMM from planes) -> Q/K/V planes
    gemm_bf16<<<dim3(MROWS/128, EMD/128, 3), 256>>>(
        xh, xl,
        wqh, wql, bq, (float*)0, Qh, Ql,
        wkh, wkl, bk, (float*)0, Kh, Kl,
        wvh, wvl, bv, (float*)0, Vh, Vl);

    // 2) Fused head-axis-softmax attention, split-K4, pipelined cp.async
    attn_kernel<<<dim3(SEQ/TQ, BATCH, KSPLIT), 256, smem_bytes>>>();

    // 3) Sum split-K partials -> O hi/lo planes
    presum_o<<<2048, 256>>>();

    // 4) Output projection (split-bf16 GEMM, fp32 out) -> d_out
    gemm_bf16<<<dim3(MROWS/128, EMD/128, 1), 256>>>(
        Oh, Ol,
        woh, wol, bo, out, (uint16_t*)0, (uint16_t*)0,
        woh, wol, bo, out, (uint16_t*)0, (uint16_t*)0,
        woh, wol, bo, out, (uint16_t*)0, (uint16_t*)0);
}